// round 13
// baseline (speedup 1.0000x reference)
#include <cuda_runtime.h>
#include <math.h>

#define S_LEN  1024
#define B_SIZE 512
#define NTAG   48
#define PF     4
#define TMID   511
#define NCHUNK 64
#define CHUNK  (S_LEN / NCHUNK)

__device__ float g_fa[B_SIZE][64];
__device__ float g_bu[B_SIZE][64];
__device__ float g_Mf[B_SIZE];
__device__ float g_Mb[B_SIZE];
__device__ float g_pnum[NCHUNK][B_SIZE];
__device__ int   g_pcnt[NCHUNK][B_SIZE];

// ---- one WARP = one half-chain. blocks 0..511 fwd, 512..1023 bwd.
// Lane l owns tag pair (2l, 2l+1); lanes 24..31 dummy (E=0, w=0).
// State v[48] stored once in shared; broadcast read via 12 LDS.128;
// one __syncwarp per step; no block barriers anywhere.
__global__ void __launch_bounds__(32)
crf_fwdbwd_kernel(const float* __restrict__ emissions,
                  const int* __restrict__ mask,
                  const float* __restrict__ start_t,
                  const float* __restrict__ end_t,
                  const float* __restrict__ trans)
{
    const int dir = blockIdx.x >> 9;
    const int b   = blockIdx.x & (B_SIZE - 1);
    const int l   = threadIdx.x;
    const int j0  = 2 * l;
    const int j1  = 2 * l + 1;
    const bool act = (l < NTAG / 2);     // l < 24

    __shared__ __align__(16) float v_sh[2][48];

    // E0[k] -> output j0, E1[k] -> output j1 over input k
    // fwd: E0[k]=exp(T[k][j0]) ; bwd: E0[k]=exp(T[j0][k])
    float E0[NTAG], E1[NTAG];
#pragma unroll
    for (int k = 0; k < NTAG; k++) {
        if (dir == 0) {
            E0[k] = act ? __expf(trans[k * NTAG + j0]) : 0.f;
            E1[k] = act ? __expf(trans[k * NTAG + j1]) : 0.f;
        } else {
            E0[k] = act ? __expf(trans[j0 * NTAG + k]) : 0.f;
            E1[k] = act ? __expf(trans[j1 * NTAG + k]) : 0.f;
        }
    }

    float M = 0.f;
    int nupd = 0;
    float w0, w1;
    float2 pf[PF];
    unsigned mbits;
    int cur = 0;

    if (dir == 0) {
        // ---- forward: t = 0 ----
        float2 em = act ? *(const float2*)(emissions + (size_t)b * NTAG + j0)
                        : make_float2(0.f, 0.f);
        w0 = act ? __expf(start_t[j0] + em.x) : 0.f;
        w1 = act ? __expf(start_t[act ? j1 : 0] + em.y) : 0.f;
        if (act) *(float2*)(&v_sh[0][j0]) = make_float2(w0, w1);
#pragma unroll
        for (int k = 0; k < PF; k++) {
            int t = 1 + k;
            pf[t & (PF - 1)] = act ? *(const float2*)(emissions + ((size_t)t * B_SIZE + b) * NTAG + j0)
                                   : make_float2(0.f, 0.f);
        }
        {
            int mt = mask[(size_t)l * B_SIZE + b];
            mbits = __ballot_sync(0xffffffffu, mt != 0);
        }
        __syncwarp();

        for (int t = 1; t <= TMID; t++) {
            if ((t & 31) == 0) {
                int mt = mask[(size_t)(t + l) * B_SIZE + b];
                mbits = __ballot_sync(0xffffffffu, mt != 0);
            }
            const int m_t = (mbits >> (t & 31)) & 1;

            const int slot = t & (PF - 1);
            const float e0 = __expf(pf[slot].x);
            const float e1 = __expf(pf[slot].y);
            int tn = t + PF; if (tn > TMID) tn = TMID;
            pf[slot] = act ? *(const float2*)(emissions + ((size_t)tn * B_SIZE + b) * NTAG + j0)
                           : make_float2(0.f, 0.f);

            const float* vv = v_sh[cur];
            float a0 = 0.f, a1 = 0.f, a2 = 0.f, a3 = 0.f;   // output j0
            float c0 = 0.f, c1 = 0.f, c2 = 0.f, c3 = 0.f;   // output j1
#pragma unroll
            for (int k = 0; k < NTAG; k += 4) {
                const float4 v4 = *(const float4*)(vv + k);
                a0 = fmaf(v4.x, E0[k + 0], a0);
                a1 = fmaf(v4.y, E0[k + 1], a1);
                a2 = fmaf(v4.z, E0[k + 2], a2);
                a3 = fmaf(v4.w, E0[k + 3], a3);
                c0 = fmaf(v4.x, E1[k + 0], c0);
                c1 = fmaf(v4.y, E1[k + 1], c1);
                c2 = fmaf(v4.z, E1[k + 2], c2);
                c3 = fmaf(v4.w, E1[k + 3], c3);
            }
            float nw0 = ((a0 + a1) + (a2 + a3)) * e0;
            float nw1 = ((c0 + c1) + (c2 + c3)) * e1;

            if (m_t) {
                w0 = nw0; w1 = nw1;
                if (((++nupd) & 7) == 0) {
                    float r = fmaxf(w0, w1);
#pragma unroll
                    for (int o = 16; o > 0; o >>= 1)
                        r = fmaxf(r, __shfl_xor_sync(0xffffffffu, r, o));
                    r = fmaxf(r, 1e-30f);
                    M += __logf(r);
                    float inv = 1.f / r;
                    w0 *= inv; w1 *= inv;
                }
            }
            if (act) *(float2*)(&v_sh[cur ^ 1][j0]) = make_float2(w0, w1);
            __syncwarp();
            cur ^= 1;
        }
        if (act) {
            g_fa[b][j0] = w0;
            g_fa[b][j1] = w1;
        }
        if (l == 0) g_Mf[b] = M;
    } else {
        // ---- backward: t = 1023 init; u = exp(end), z = u * exp(em[1023]) ----
        float2 em = act ? *(const float2*)(emissions + ((size_t)(S_LEN - 1) * B_SIZE + b) * NTAG + j0)
                        : make_float2(0.f, 0.f);
        w0 = act ? __expf(end_t[j0]) : 0.f;
        w1 = act ? __expf(end_t[act ? j1 : 0]) : 0.f;
        if (act) *(float2*)(&v_sh[0][j0]) = make_float2(w0 * __expf(em.x), w1 * __expf(em.y));
#pragma unroll
        for (int k = 0; k < PF; k++) {
            int t = 1022 - k;
            pf[t & (PF - 1)] = act ? *(const float2*)(emissions + ((size_t)t * B_SIZE + b) * NTAG + j0)
                                   : make_float2(0.f, 0.f);
        }
        {
            int mt = mask[(size_t)(992 + l) * B_SIZE + b];
            mbits = __ballot_sync(0xffffffffu, mt != 0);
        }
        __syncwarp();

        for (int tt = S_LEN - 1; tt > TMID; tt--) {
            const int m_t = (mbits >> (tt & 31)) & 1;   // mask[tt]

            const int tm1 = tt - 1;
            const int slot = tm1 & (PF - 1);
            const float e0 = __expf(pf[slot].x);        // exp(em[tt-1]) pair
            const float e1 = __expf(pf[slot].y);
            int tn = tm1 - PF; if (tn < TMID) tn = TMID;
            pf[slot] = act ? *(const float2*)(emissions + ((size_t)tn * B_SIZE + b) * NTAG + j0)
                           : make_float2(0.f, 0.f);

            if (m_t) {
                const float* vv = v_sh[cur];
                float a0 = 0.f, a1 = 0.f, a2 = 0.f, a3 = 0.f;
                float c0 = 0.f, c1 = 0.f, c2 = 0.f, c3 = 0.f;
#pragma unroll
                for (int k = 0; k < NTAG; k += 4) {
                    const float4 v4 = *(const float4*)(vv + k);
                    a0 = fmaf(v4.x, E0[k + 0], a0);
                    a1 = fmaf(v4.y, E0[k + 1], a1);
                    a2 = fmaf(v4.z, E0[k + 2], a2);
                    a3 = fmaf(v4.w, E0[k + 3], a3);
                    c0 = fmaf(v4.x, E1[k + 0], c0);
                    c1 = fmaf(v4.y, E1[k + 1], c1);
                    c2 = fmaf(v4.z, E1[k + 2], c2);
                    c3 = fmaf(v4.w, E1[k + 3], c3);
                }
                w0 = (a0 + a1) + (a2 + a3);
                w1 = (c0 + c1) + (c2 + c3);
                if (((++nupd) & 7) == 0) {
                    float r = fmaxf(w0, w1);
#pragma unroll
                    for (int o = 16; o > 0; o >>= 1)
                        r = fmaxf(r, __shfl_xor_sync(0xffffffffu, r, o));
                    r = fmaxf(r, 1e-30f);
                    M += __logf(r);
                    float inv = 1.f / r;
                    w0 *= inv; w1 *= inv;
                }
            }
            // z_{tt-1} = u * exp(em[tt-1]) — always from registers (mask-safe)
            if (act) *(float2*)(&v_sh[cur ^ 1][j0]) = make_float2(w0 * e0, w1 * e1);
            __syncwarp();
            cur ^= 1;
            if (((tt - 1) & 31) == 31) {
                int base = tt - 32;
                int mt = mask[(size_t)(base + l) * B_SIZE + b];
                mbits = __ballot_sync(0xffffffffu, mt != 0);
            }
        }
        if (act) {
            g_bu[b][j0] = w0;
            g_bu[b][j1] = w1;
        }
        if (l == 0) g_Mb[b] = M;
    }
}

// ---- numerator partials: coalesced over batch, 64-way parallel over t ----
__global__ void __launch_bounds__(B_SIZE)
crf_num_kernel(const float* __restrict__ emissions,
               const int* __restrict__ tags,
               const int* __restrict__ mask,
               const float* __restrict__ start_t,
               const float* __restrict__ trans)
{
    const int b  = threadIdx.x;
    const int c  = blockIdx.x;
    const int t0 = c * CHUNK;

    float acc = 0.f;
    int cnt = 0;
    int tp = (t0 > 0) ? tags[(t0 - 1) * B_SIZE + b] : 0;
#pragma unroll
    for (int k = 0; k < CHUNK; k++) {
        int t  = t0 + k;
        int tg = tags[t * B_SIZE + b];
        int m  = mask[t * B_SIZE + b];
        cnt += m;
        if (t == 0) {
            acc += start_t[tg] + emissions[(size_t)b * NTAG + tg];
        } else {
            acc += (trans[tp * NTAG + tg] +
                    emissions[((size_t)t * B_SIZE + b) * NTAG + tg]) * (float)m;
        }
        tp = tg;
    }
    g_pnum[c][b] = acc;
    g_pcnt[c][b] = cnt;
}

// ---- final: end-term + alpha.beta dot + mean ----
__global__ void __launch_bounds__(B_SIZE)
crf_reduce_kernel(float* __restrict__ out,
                  const int* __restrict__ tags,
                  const float* __restrict__ end_t)
{
    __shared__ float sh[B_SIZE];
    const int b = threadIdx.x;

    float num = 0.f;
    int cnt = 0;
#pragma unroll
    for (int c = 0; c < NCHUNK; c++) { num += g_pnum[c][b]; cnt += g_pcnt[c][b]; }
    num += end_t[tags[(cnt - 1) * B_SIZE + b]];

    float dot = 0.f;
    const float4* fa = (const float4*)g_fa[b];
    const float4* bu = (const float4*)g_bu[b];
#pragma unroll
    for (int k = 0; k < 12; k++) {
        float4 x = fa[k], y = bu[k];
        dot += x.x * y.x + x.y * y.y + x.z * y.z + x.w * y.w;
    }
    const float den = g_Mf[b] + g_Mb[b] + __logf(dot);

    sh[b] = num - den;
    __syncthreads();
#pragma unroll
    for (int o = B_SIZE / 2; o > 0; o >>= 1) {
        if (b < o) sh[b] += sh[b + o];
        __syncthreads();
    }
    if (b == 0) out[0] = sh[0] * (1.f / (float)B_SIZE);
}

extern "C" void kernel_launch(void* const* d_in, const int* in_sizes, int n_in,
                              void* d_out, int out_size)
{
    const float* emissions = (const float*)d_in[0];
    const int*   tags      = (const int*)d_in[1];
    const int*   mask      = (const int*)d_in[2];
    const float* start_t   = (const float*)d_in[3];
    const float* end_t     = (const float*)d_in[4];
    const float* trans     = (const float*)d_in[5];

    crf_fwdbwd_kernel<<<2 * B_SIZE, 32>>>(emissions, mask, start_t, end_t, trans);
    crf_num_kernel<<<NCHUNK, B_SIZE>>>(emissions, tags, mask, start_t, trans);
    crf_reduce_kernel<<<1, B_SIZE>>>((float*)d_out, tags, end_t);
}